// round 1
// baseline (speedup 1.0000x reference)
#include <cuda_runtime.h>
#include <cuda_bf16.h>
#include <cstdint>

// Problem constants
#define BB 4096
#define SS 64
#define EE 128
#define HH 256
#define CC 18

#define BM 32      // batch rows per block
#define KT 16      // k-tile
#define NTHREADS 256

// Scratch (allocation-free rule: static __device__ arrays)
__device__ float g_xw[SS * BB * HH];   // [t][b][h], 256 MB
__device__ float g_last[BB * HH];      // final hidden per row, 4 MB

// ---------------------------------------------------------------------------
// Kernel 1: xW[t][b][h] = b_ih[h] + sum_e emb[x_in[b][t]][e] * W_ih[h][e]
// grid: (B/BM, S), 256 threads
// ---------------------------------------------------------------------------
__global__ __launch_bounds__(NTHREADS) void proj_kernel(
    const int* __restrict__ x_in,
    const float* __restrict__ emb,
    const float* __restrict__ W_ih,
    const float* __restrict__ b_ih)
{
    __shared__ float Asm[BM][EE];   // gathered embedding rows (16 KB)
    __shared__ float Wt[KT][HH];    // W_ih k-tile, transposed (16 KB)

    const int t   = blockIdx.y;
    const int b0  = blockIdx.x * BM;
    const int tid = threadIdx.x;

    // Gather 32 embedding rows: 8 threads/row, 16 floats/thread
    {
        const int r   = tid >> 3;
        const int seg = tid & 7;
        const int idx = x_in[(b0 + r) * SS + t];
        const float4* src = reinterpret_cast<const float4*>(emb + (size_t)idx * EE + seg * 16);
        float4* dst = reinterpret_cast<float4*>(&Asm[r][seg * 16]);
#pragma unroll
        for (int q = 0; q < 4; q++) dst[q] = src[q];
    }

    const int r_t = tid >> 5;   // 0..7  (warp id)
    const int c_t = tid & 31;   // 0..31

    float acc[4][8];
    {
        float4 bl = *reinterpret_cast<const float4*>(b_ih + c_t * 8);
        float4 bh = *reinterpret_cast<const float4*>(b_ih + c_t * 8 + 4);
        float bias[8] = {bl.x, bl.y, bl.z, bl.w, bh.x, bh.y, bh.z, bh.w};
#pragma unroll
        for (int i = 0; i < 4; i++)
#pragma unroll
            for (int j = 0; j < 8; j++) acc[i][j] = bias[j];
    }

    const int kk4   = tid & 3;
    const int cbase = tid >> 2;

    for (int k0 = 0; k0 < EE; k0 += KT) {
        __syncthreads();
        // load W_ih tile transposed: Wt[kk][c] = W_ih[c][k0+kk]
#pragma unroll
        for (int q = 0; q < 4; q++) {
            const int c = cbase + 64 * q;
            float4 v = *reinterpret_cast<const float4*>(W_ih + (size_t)c * EE + k0 + kk4 * 4);
            Wt[kk4 * 4 + 0][c] = v.x;
            Wt[kk4 * 4 + 1][c] = v.y;
            Wt[kk4 * 4 + 2][c] = v.z;
            Wt[kk4 * 4 + 3][c] = v.w;
        }
        __syncthreads();
#pragma unroll
        for (int kk = 0; kk < KT; kk++) {
            float a[4];
#pragma unroll
            for (int i = 0; i < 4; i++) a[i] = Asm[r_t * 4 + i][k0 + kk];
            float w[8];
            *reinterpret_cast<float4*>(w)     = *reinterpret_cast<const float4*>(&Wt[kk][c_t * 8]);
            *reinterpret_cast<float4*>(w + 4) = *reinterpret_cast<const float4*>(&Wt[kk][c_t * 8 + 4]);
#pragma unroll
            for (int i = 0; i < 4; i++)
#pragma unroll
                for (int j = 0; j < 8; j++) acc[i][j] += a[i] * w[j];
        }
    }

    // write out: g_xw[(t*B + b)*H + h]
#pragma unroll
    for (int i = 0; i < 4; i++) {
        float* dst = &g_xw[((size_t)t * BB + b0 + r_t * 4 + i) * HH + c_t * 8];
        *reinterpret_cast<float4*>(dst)     = *reinterpret_cast<float4*>(&acc[i][0]);
        *reinterpret_cast<float4*>(dst + 4) = *reinterpret_cast<float4*>(&acc[i][4]);
    }
}

// ---------------------------------------------------------------------------
// Kernel 2: RNN scan. Each block owns 32 batch rows for all 64 steps.
// h_new = tanh(xw[t] + h @ W_hh^T + b_hh); saves h at t == len-1.
// grid: B/BM, 256 threads
// ---------------------------------------------------------------------------
__global__ __launch_bounds__(NTHREADS) void rnn_kernel(
    const int* __restrict__ x_lengths,
    const float* __restrict__ W_hh,
    const float* __restrict__ b_hh)
{
    __shared__ float Hs[BM][HH];    // current hidden (32 KB)
    __shared__ float Wt[KT][HH];    // W_hh k-tile (16 KB)

    const int b0  = blockIdx.x * BM;
    const int tid = threadIdx.x;
    const int r_t = tid >> 5;
    const int c_t = tid & 31;

    // zero h0
    for (int i = tid; i < BM * HH; i += NTHREADS) (&Hs[0][0])[i] = 0.0f;

    float bbh[8];
    {
        float4 bl = *reinterpret_cast<const float4*>(b_hh + c_t * 8);
        float4 bh = *reinterpret_cast<const float4*>(b_hh + c_t * 8 + 4);
        bbh[0]=bl.x; bbh[1]=bl.y; bbh[2]=bl.z; bbh[3]=bl.w;
        bbh[4]=bh.x; bbh[5]=bh.y; bbh[6]=bh.z; bbh[7]=bh.w;
    }
    int rl[4];
#pragma unroll
    for (int i = 0; i < 4; i++) rl[i] = x_lengths[b0 + r_t * 4 + i];

    const int kk4   = tid & 3;
    const int cbase = tid >> 2;

    __syncthreads();

    for (int t = 0; t < SS; t++) {
        float acc[4][8];
        // init accumulator from precomputed input projection (includes b_ih)
#pragma unroll
        for (int i = 0; i < 4; i++) {
            const float* xr = &g_xw[((size_t)t * BB + b0 + r_t * 4 + i) * HH + c_t * 8];
            *reinterpret_cast<float4*>(&acc[i][0]) = *reinterpret_cast<const float4*>(xr);
            *reinterpret_cast<float4*>(&acc[i][4]) = *reinterpret_cast<const float4*>(xr + 4);
        }

        for (int k0 = 0; k0 < HH; k0 += KT) {
            __syncthreads();
#pragma unroll
            for (int q = 0; q < 4; q++) {
                const int c = cbase + 64 * q;
                float4 v = *reinterpret_cast<const float4*>(W_hh + (size_t)c * HH + k0 + kk4 * 4);
                Wt[kk4 * 4 + 0][c] = v.x;
                Wt[kk4 * 4 + 1][c] = v.y;
                Wt[kk4 * 4 + 2][c] = v.z;
                Wt[kk4 * 4 + 3][c] = v.w;
            }
            __syncthreads();
#pragma unroll
            for (int kk = 0; kk < KT; kk++) {
                float a[4];
#pragma unroll
                for (int i = 0; i < 4; i++) a[i] = Hs[r_t * 4 + i][k0 + kk];
                float w[8];
                *reinterpret_cast<float4*>(w)     = *reinterpret_cast<const float4*>(&Wt[kk][c_t * 8]);
                *reinterpret_cast<float4*>(w + 4) = *reinterpret_cast<const float4*>(&Wt[kk][c_t * 8 + 4]);
#pragma unroll
                for (int i = 0; i < 4; i++)
#pragma unroll
                    for (int j = 0; j < 8; j++) acc[i][j] += a[i] * w[j];
            }
        }
        __syncthreads();  // all reads of Hs done before overwriting

#pragma unroll
        for (int i = 0; i < 4; i++) {
            float hv[8];
#pragma unroll
            for (int j = 0; j < 8; j++) hv[j] = tanhf(acc[i][j] + bbh[j]);
            float* hd = &Hs[r_t * 4 + i][c_t * 8];
            *reinterpret_cast<float4*>(hd)     = *reinterpret_cast<float4*>(&hv[0]);
            *reinterpret_cast<float4*>(hd + 4) = *reinterpret_cast<float4*>(&hv[4]);
            if (t == rl[i] - 1) {
                float* dst = &g_last[(size_t)(b0 + r_t * 4 + i) * HH + c_t * 8];
                *reinterpret_cast<float4*>(dst)     = *reinterpret_cast<float4*>(&hv[0]);
                *reinterpret_cast<float4*>(dst + 4) = *reinterpret_cast<float4*>(&hv[4]);
            }
        }
    }
}

// ---------------------------------------------------------------------------
// Kernel 3: out = relu(last @ W1^T + b1) @ W2^T + b2
// grid: B/BM, 256 threads
// ---------------------------------------------------------------------------
__global__ __launch_bounds__(NTHREADS) void fc_kernel(
    const float* __restrict__ W1,
    const float* __restrict__ b1,
    const float* __restrict__ W2,
    const float* __restrict__ b2,
    float* __restrict__ out)
{
    __shared__ float Asm[BM][HH];   // last hidden, then relu(y)
    __shared__ float Wt[KT][HH];

    const int b0  = blockIdx.x * BM;
    const int tid = threadIdx.x;
    const int r_t = tid >> 5;
    const int c_t = tid & 31;

    for (int i = tid; i < BM * HH; i += NTHREADS)
        (&Asm[0][0])[i] = g_last[(size_t)b0 * HH + i];

    float acc[4][8];
    {
        float4 bl = *reinterpret_cast<const float4*>(b1 + c_t * 8);
        float4 bh = *reinterpret_cast<const float4*>(b1 + c_t * 8 + 4);
        float bias[8] = {bl.x, bl.y, bl.z, bl.w, bh.x, bh.y, bh.z, bh.w};
#pragma unroll
        for (int i = 0; i < 4; i++)
#pragma unroll
            for (int j = 0; j < 8; j++) acc[i][j] = bias[j];
    }

    const int kk4   = tid & 3;
    const int cbase = tid >> 2;

    for (int k0 = 0; k0 < HH; k0 += KT) {
        __syncthreads();
#pragma unroll
        for (int q = 0; q < 4; q++) {
            const int c = cbase + 64 * q;
            float4 v = *reinterpret_cast<const float4*>(W1 + (size_t)c * HH + k0 + kk4 * 4);
            Wt[kk4 * 4 + 0][c] = v.x;
            Wt[kk4 * 4 + 1][c] = v.y;
            Wt[kk4 * 4 + 2][c] = v.z;
            Wt[kk4 * 4 + 3][c] = v.w;
        }
        __syncthreads();
#pragma unroll
        for (int kk = 0; kk < KT; kk++) {
            float a[4];
#pragma unroll
            for (int i = 0; i < 4; i++) a[i] = Asm[r_t * 4 + i][k0 + kk];
            float w[8];
            *reinterpret_cast<float4*>(w)     = *reinterpret_cast<const float4*>(&Wt[kk][c_t * 8]);
            *reinterpret_cast<float4*>(w + 4) = *reinterpret_cast<const float4*>(&Wt[kk][c_t * 8 + 4]);
#pragma unroll
            for (int i = 0; i < 4; i++)
#pragma unroll
                for (int j = 0; j < 8; j++) acc[i][j] += a[i] * w[j];
        }
    }
    __syncthreads();  // done reading Asm (last hidden)

    // relu, write y back into Asm
#pragma unroll
    for (int i = 0; i < 4; i++) {
        float yv[8];
#pragma unroll
        for (int j = 0; j < 8; j++) yv[j] = fmaxf(acc[i][j], 0.0f);
        float* yd = &Asm[r_t * 4 + i][c_t * 8];
        *reinterpret_cast<float4*>(yd)     = *reinterpret_cast<float4*>(&yv[0]);
        *reinterpret_cast<float4*>(yd + 4) = *reinterpret_cast<float4*>(&yv[4]);
    }
    __syncthreads();

    // layer 2: out[r][c] = b2[c] + sum_k y[r][k] * W2[c][k]
    for (int e = tid; e < BM * CC; e += NTHREADS) {
        const int r = e / CC;
        const int c = e % CC;
        const float4* yv = reinterpret_cast<const float4*>(&Asm[r][0]);
        const float4* wv = reinterpret_cast<const float4*>(W2 + (size_t)c * HH);
        float s = b2[c];
#pragma unroll 8
        for (int k = 0; k < HH / 4; k++) {
            float4 a = yv[k];
            float4 w = wv[k];
            s += a.x * w.x + a.y * w.y + a.z * w.z + a.w * w.w;
        }
        out[(size_t)(b0 + r) * CC + c] = s;
    }
}

// ---------------------------------------------------------------------------
extern "C" void kernel_launch(void* const* d_in, const int* in_sizes, int n_in,
                              void* d_out, int out_size)
{
    const int*   x_in  = (const int*)  d_in[0];
    const int*   x_len = (const int*)  d_in[1];
    const float* emb   = (const float*)d_in[2];
    const float* W_ih  = (const float*)d_in[3];
    const float* W_hh  = (const float*)d_in[4];
    const float* b_ih  = (const float*)d_in[5];
    const float* b_hh  = (const float*)d_in[6];
    const float* W1    = (const float*)d_in[7];
    const float* b1    = (const float*)d_in[8];
    const float* W2    = (const float*)d_in[9];
    const float* b2    = (const float*)d_in[10];
    float* out = (float*)d_out;

    dim3 gp(BB / BM, SS);
    proj_kernel<<<gp, NTHREADS>>>(x_in, emb, W_ih, b_ih);
    rnn_kernel<<<BB / BM, NTHREADS>>>(x_len, W_hh, b_hh);
    fc_kernel<<<BB / BM, NTHREADS>>>(W1, b1, W2, b2, out);
}